// round 4
// baseline (speedup 1.0000x reference)
#include <cuda_runtime.h>
#include <cuda_bf16.h>
#include <stdint.h>

#define HDIM   256
#define BATCH  32
#define TSTEPS 4096
#define EDGES  8192
#define D2     512
#define MTOT   (TSTEPS * BATCH)   // 131072

// ---------------- scratch (static device globals; no runtime alloc) ----------------
__device__ __align__(16) float          g_p[BATCH * D2];    // W1*hidden + b_attn  [b][d]
__device__ __align__(16) __nv_bfloat16  g_W2b[D2 * HDIM];   // bf16(W_attn[:,256:512]) [n][k]
__device__ __align__(16) float          g_e[MTOT];          // exp(score)  [t*32 + b]
__device__ __align__(16) float          g_sum[BATCH];       // per-batch softmax denom

__device__ __forceinline__ uint32_t smem_u32(const void* p) {
    uint32_t a;
    asm("{ .reg .u64 t; cvta.to.shared.u64 t, %1; cvt.u32.u64 %0, t; }" : "=r"(a) : "l"(p));
    return a;
}
__device__ __forceinline__ float tanh_fast(float x) {
    float t;
    asm("tanh.approx.f32 %0, %1;" : "=f"(t) : "f"(x));
    return t;
}
__device__ __forceinline__ void cp_async16(uint32_t dst, const void* src) {
    asm volatile("cp.async.ca.shared.global [%0], [%1], 16;" :: "r"(dst), "l"(src));
}
#define CP_COMMIT() asm volatile("cp.async.commit_group;" ::: "memory")
#define CP_WAIT(n)  asm volatile("cp.async.wait_group %0;" :: "n"(n) : "memory")

// ---------------- kernel 1a: p = W1*hidden + b_attn (warp-per-output) ----------------
__global__ void prep_p_kernel(const float* __restrict__ hidden,
                              const float* __restrict__ W,
                              const float* __restrict__ ba) {
    int tid = threadIdx.x, lid = tid & 31;
    int gw = blockIdx.x * 8 + (tid >> 5);        // 2048 blocks x 8 warps = 16384 outputs
    int b = gw >> 9, d = gw & 511;
    const float* wr = W + (size_t)d * 512;       // W1 = W_attn[:, 0:256]
    const float* hr = hidden + b * HDIM;
    float s = 0.f;
    #pragma unroll
    for (int k = lid; k < HDIM; k += 32) s += wr[k] * hr[k];
    #pragma unroll
    for (int o = 16; o > 0; o >>= 1) s += __shfl_xor_sync(0xFFFFFFFF, s, o);
    if (lid == 0) g_p[gw] = s + ba[d];           // gw == b*512 + d
}

// ---------------- kernel 1b: W2 -> bf16 ; zero d_out / g_sum ----------------
__global__ void prep_w2_kernel(const float* __restrict__ W, float* __restrict__ out) {
    int gt = blockIdx.x * 256 + threadIdx.x;     // 512 blocks x 256 = 131072
    int n = gt >> 8, k = gt & 255;
    g_W2b[gt] = __float2bfloat16(W[(size_t)n * 512 + HDIM + k]);
    out[gt] = 0.f;
    if (gt < BATCH) g_sum[gt] = 0.f;
}

// ---------------- kernel 2: mma.sync bf16 GEMM, pipelined, fused epilogue ----------------
// CTA: 128 M-rows, 8 warps (warp tile 16x32), 16 N-chunks of 32, 2-stage cp.async, occ 2.
static constexpr int SM_A     = 0;        // 128 rows x 512 B (bf16 k=256, swizzled) = 65536
static constexpr int SM_B0    = 65536;    // 32 rows x 512 B = 16384
static constexpr int SM_B1    = 81920;
static constexpr int SM_P0    = 98304;    // 32 x 36 floats = 4608
static constexpr int SM_P1    = 102912;
static constexpr int SM_V     = 107520;   // 512 floats = 2048
static constexpr int SM_BS    = 109568;   // 32 floats
static constexpr int SM_TOTAL = 109696;

__device__ __forceinline__ void load_chunk(uint32_t sb, int c, int buf, int tid) {
    const char* bsrc = (const char*)(g_W2b + (size_t)c * 32 * HDIM);   // 16 KB
    uint32_t bdst = sb + (buf ? SM_B1 : SM_B0);
    #pragma unroll
    for (int i = tid; i < 1024; i += 256) {
        int row = i >> 5, k16 = i & 31;
        cp_async16(bdst + row * 512 + ((k16 ^ (row & 7)) << 4), bsrc + i * 16);
    }
    // p chunk [32 b][32 cols], smem stride 36 floats (144 B)
    int pb = tid >> 3, j16 = tid & 7;
    cp_async16(sb + (buf ? SM_P1 : SM_P0) + pb * 144 + j16 * 16,
               (const char*)(g_p + pb * 512 + c * 32 + j16 * 4));
}

__global__ __launch_bounds__(256, 2)
void attn_gemm_kernel(const float* __restrict__ enc, const float* __restrict__ v) {
    extern __shared__ char smem[];
    uint32_t sb = smem_u32(smem);
    int tid = threadIdx.x, wid = tid >> 5, lid = tid & 31;
    int gid = lid >> 2, tg = lid & 3;

    float* v_s  = (float*)(smem + SM_V);
    float* bsum = (float*)(smem + SM_BS);
    if (tid < 32) bsum[tid] = 0.f;

    // ---- prologue: chunk 0 (+v) then chunk 1 in flight ----
    load_chunk(sb, 0, 0, tid);
    if (tid < 128) cp_async16(sb + SM_V + tid * 16, (const char*)(v + tid * 4));
    CP_COMMIT();
    load_chunk(sb, 1, 1, tid);
    CP_COMMIT();

    // ---- A: enc rows [blk*128, +128): fp32 -> bf16, swizzled smem ----
    const float4* asrc = (const float4*)(enc + (size_t)blockIdx.x * 128 * HDIM);
    for (int i = tid; i < 4096; i += 256) {
        int row = i >> 5, k16 = i & 31;
        float4 a = asrc[row * 64 + k16 * 2];
        float4 b = asrc[row * 64 + k16 * 2 + 1];
        __nv_bfloat162 t0 = __floats2bfloat162_rn(a.x, a.y);
        __nv_bfloat162 t1 = __floats2bfloat162_rn(a.z, a.w);
        __nv_bfloat162 t2 = __floats2bfloat162_rn(b.x, b.y);
        __nv_bfloat162 t3 = __floats2bfloat162_rn(b.z, b.w);
        uint4 val;
        val.x = *reinterpret_cast<uint32_t*>(&t0);
        val.y = *reinterpret_cast<uint32_t*>(&t1);
        val.z = *reinterpret_cast<uint32_t*>(&t2);
        val.w = *reinterpret_cast<uint32_t*>(&t3);
        *reinterpret_cast<uint4*>(smem + SM_A + row * 512 + ((k16 ^ (row & 7)) << 4)) = val;
    }

    // ---- per-lane ldmatrix addressing (layout validated R2/R3) ----
    int arow = wid * 16 + (lid & 7) + (lid & 8);
    uint32_t aoff = sb + SM_A + arow * 512;
    uint32_t asw  = (uint32_t)(arow & 7);
    uint32_t ahalf = (lid >> 4) & 1;
    int bn = (lid & 7) + (((lid >> 4) & 1) << 3);      // 0..15
    uint32_t bsw  = (uint32_t)(bn & 7);
    uint32_t bhalf = (lid >> 3) & 1;

    float rs[2] = {0.f, 0.f};

    for (int c = 0; c < 16; c++) {
        int cur = c & 1;
        if (c < 15) { CP_WAIT(1); } else { CP_WAIT(0); }
        __syncthreads();                       // chunk c data + (c==0) A stores visible

        uint32_t boff = sb + (cur ? SM_B1 : SM_B0) + bn * 512;
        const float* p_s = (const float*)(smem + (cur ? SM_P1 : SM_P0));

        float acc[4][4];
        #pragma unroll
        for (int j = 0; j < 4; j++)
            #pragma unroll
            for (int r = 0; r < 4; r++) acc[j][r] = 0.f;

        #pragma unroll
        for (int kk = 0; kk < 16; kk++) {
            uint32_t ak = (((2u * kk + ahalf) ^ asw) << 4);
            uint32_t bk = (((2u * kk + bhalf) ^ bsw) << 4);
            uint32_t a[4], br[8];
            asm volatile("ldmatrix.sync.aligned.m8n8.x4.shared.b16 {%0,%1,%2,%3}, [%4];"
                : "=r"(a[0]), "=r"(a[1]), "=r"(a[2]), "=r"(a[3]) : "r"(aoff + ak));
            #pragma unroll
            for (int t = 0; t < 2; t++) {
                asm volatile("ldmatrix.sync.aligned.m8n8.x4.shared.b16 {%0,%1,%2,%3}, [%4];"
                    : "=r"(br[4 * t]), "=r"(br[4 * t + 1]),
                      "=r"(br[4 * t + 2]), "=r"(br[4 * t + 3])
                    : "r"(boff + (uint32_t)t * 8192 + bk));
            }
            #pragma unroll
            for (int j = 0; j < 4; j++) {
                asm volatile(
                    "mma.sync.aligned.m16n8k16.row.col.f32.bf16.bf16.f32 "
                    "{%0,%1,%2,%3}, {%4,%5,%6,%7}, {%8,%9}, {%0,%1,%2,%3};"
                    : "+f"(acc[j][0]), "+f"(acc[j][1]), "+f"(acc[j][2]), "+f"(acc[j][3])
                    : "r"(a[0]), "r"(a[1]), "r"(a[2]), "r"(a[3]),
                      "r"(br[2 * j]), "r"(br[2 * j + 1]));
            }
        }

        // ---- fused epilogue: += v[col] * tanh(acc + p[b][col]) ----
        const float* vc = v_s + c * 32;
        #pragma unroll
        for (int r = 0; r < 4; r++) {
            int rh = r >> 1;
            int bix = (wid * 16 + gid + (rh << 3)) & 31;
            const float* pr = p_s + bix * 36;
            float s = 0.f;
            #pragma unroll
            for (int j = 0; j < 4; j++) {
                int lcol = j * 8 + tg * 2 + (r & 1);
                s += vc[lcol] * tanh_fast(acc[j][r] + pr[lcol]);
            }
            rs[rh] += s;
        }

        __syncthreads();                       // all warps done reading buf[cur]
        if (c + 2 < 16) {
            load_chunk(sb, c + 2, cur, tid);
            CP_COMMIT();
        }
    }

    // quad reduction (lanes share gid, differ in tg)
    #pragma unroll
    for (int h = 0; h < 2; h++) {
        float x = rs[h];
        x += __shfl_xor_sync(0xFFFFFFFF, x, 1);
        x += __shfl_xor_sync(0xFFFFFFFF, x, 2);
        rs[h] = x;
    }
    if (tg == 0) {
        int m = blockIdx.x * 128 + wid * 16 + gid;
        float e0 = __expf(rs[0]);
        float e1 = __expf(rs[1]);
        g_e[m]     = e0;
        g_e[m + 8] = e1;
        atomicAdd(&bsum[m & 31], e0);
        atomicAdd(&bsum[(m + 8) & 31], e1);
    }
    __syncthreads();
    if (tid < 32) atomicAdd(&g_sum[tid], bsum[tid]);
}

// ---------------- kernel 3: masked edge scatter-add with softmax divide, x0.1 ----------------
__global__ void scatter_kernel(const int* __restrict__ esrc,
                               const int* __restrict__ edst,
                               float* __restrict__ out) {
    int i = blockIdx.x * 256 + threadIdx.x;
    if (i >= BATCH * EDGES) return;
    int b = i >> 13;                    // EDGES = 8192
    int s = esrc[i], d = edst[i];
    if (d != s + 1) {
        float w = 0.1f * __fdividef(g_e[s * 32 + b], g_sum[b]);
        atomicAdd(out + b * TSTEPS + d, w);
    }
}

// ---------------- host launch ----------------
extern "C" void kernel_launch(void* const* d_in, const int* in_sizes, int n_in,
                              void* d_out, int out_size) {
    const float* hidden = (const float*)d_in[0];
    const float* enc    = (const float*)d_in[1];
    const int*   esrc   = (const int*)d_in[2];
    const int*   edst   = (const int*)d_in[3];
    const float* W      = (const float*)d_in[4];
    const float* ba     = (const float*)d_in[5];
    const float* v      = (const float*)d_in[6];
    float* out = (float*)d_out;

    cudaFuncSetAttribute(attn_gemm_kernel,
                         cudaFuncAttributeMaxDynamicSharedMemorySize, SM_TOTAL);

    prep_p_kernel<<<2048, 256>>>(hidden, W, ba);
    prep_w2_kernel<<<512, 256>>>(W, out);
    attn_gemm_kernel<<<MTOT / 128, 256, SM_TOTAL>>>(enc, v);
    scatter_kernel<<<(BATCH * EDGES + 255) / 256, 256>>>(esrc, edst, out);
}

// round 5
// speedup vs baseline: 1.0939x; 1.0939x over previous
#include <cuda_runtime.h>
#include <cuda_bf16.h>
#include <cuda_fp16.h>
#include <stdint.h>

#define HDIM   256
#define BATCH  32
#define TSTEPS 4096
#define EDGES  8192
#define D2     512
#define MTOT   (TSTEPS * BATCH)   // 131072

// ---------------- scratch (static device globals; no runtime alloc) ----------------
__device__ __align__(16) float   g_p[BATCH * D2];    // W1*hidden + b_attn  [b][d]
__device__ __align__(16) __half  g_W2h[D2 * HDIM];   // fp16(W_attn[:,256:512]) [n][k]
__device__ __align__(16) float   g_e[MTOT];          // exp(score)  [t*32 + b]
__device__ __align__(16) float   g_sum[BATCH];       // per-batch softmax denom

__device__ __forceinline__ uint32_t smem_u32(const void* p) {
    uint32_t a;
    asm("{ .reg .u64 t; cvta.to.shared.u64 t, %1; cvt.u32.u64 %0, t; }" : "=r"(a) : "l"(p));
    return a;
}
__device__ __forceinline__ float tanh_fast(float x) {
    float t;
    asm("tanh.approx.f32 %0, %1;" : "=f"(t) : "f"(x));
    return t;
}
__device__ __forceinline__ void cp_async16(uint32_t dst, const void* src) {
    asm volatile("cp.async.ca.shared.global [%0], [%1], 16;" :: "r"(dst), "l"(src));
}
#define CP_COMMIT() asm volatile("cp.async.commit_group;" ::: "memory")
#define CP_WAIT0()  asm volatile("cp.async.wait_group 0;" ::: "memory")

// ---------------- kernel 1a: p = W1*hidden + b_attn (warp-per-output) ----------------
__global__ void prep_p_kernel(const float* __restrict__ hidden,
                              const float* __restrict__ W,
                              const float* __restrict__ ba) {
    int tid = threadIdx.x, lid = tid & 31;
    int gw = blockIdx.x * 8 + (tid >> 5);        // 2048 blocks x 8 warps = 16384 outputs
    int b = gw >> 9, d = gw & 511;
    const float* wr = W + (size_t)d * 512;       // W1 = W_attn[:, 0:256]
    const float* hr = hidden + b * HDIM;
    float s = 0.f;
    #pragma unroll
    for (int k = lid; k < HDIM; k += 32) s += wr[k] * hr[k];
    #pragma unroll
    for (int o = 16; o > 0; o >>= 1) s += __shfl_xor_sync(0xFFFFFFFF, s, o);
    if (lid == 0) g_p[gw] = s + ba[d];           // gw == b*512 + d
}

// ---------------- kernel 1b: W2 -> fp16 ; zero d_out / g_sum ----------------
__global__ void prep_w2_kernel(const float* __restrict__ W, float* __restrict__ out) {
    int gt = blockIdx.x * 256 + threadIdx.x;     // 512 blocks x 256 = 131072
    int n = gt >> 8, k = gt & 255;
    g_W2h[gt] = __float2half_rn(W[(size_t)n * 512 + HDIM + k]);
    out[gt] = 0.f;
    if (gt < BATCH) g_sum[gt] = 0.f;
}

// ---------------- kernel 2: mma.sync fp16 GEMM (fp16 accum, split-K promote) ----------------
// CTA: 128 M-rows, 8 warps (warp tile 16x64), 8 N-chunks of 64, occupancy 2.
static constexpr int SM_A     = 0;        // 128 rows x 512 B (fp16 k=256, swizzled) = 65536
static constexpr int SM_B     = 65536;    // 64 rows x 512 B                         = 32768
static constexpr int SM_P     = 98304;    // 32 x 68 floats                          = 8704
static constexpr int SM_V     = 107008;   // 512 floats                              = 2048
static constexpr int SM_BS    = 109056;   // 32 floats                               = 128
static constexpr int SM_TOTAL = 109184;

__global__ __launch_bounds__(256, 2)
void attn_gemm_kernel(const float* __restrict__ enc, const float* __restrict__ v) {
    extern __shared__ char smem[];
    uint32_t sb = smem_u32(smem);
    int tid = threadIdx.x, wid = tid >> 5, lid = tid & 31;
    int gid = lid >> 2, tg = lid & 3;

    float* p_s  = (float*)(smem + SM_P);
    float* v_s  = (float*)(smem + SM_V);
    float* bsum = (float*)(smem + SM_BS);
    if (tid < 32) bsum[tid] = 0.f;

    // ---- prologue: async-load B chunk 0 + p chunk 0 + v ----
    {
        const char* bsrc = (const char*)g_W2h;
        for (int i = tid; i < 2048; i += 256) {
            int row = i >> 5, k16 = i & 31;
            cp_async16(sb + SM_B + row * 512 + ((k16 ^ (row & 7)) << 4), bsrc + i * 16);
        }
        for (int i = tid; i < 512; i += 256) {
            int pb = i >> 4, j16 = i & 15;
            cp_async16(sb + SM_P + pb * 272 + j16 * 16, (const char*)(g_p + pb * 512 + j16 * 4));
        }
        if (tid < 128)
            cp_async16(sb + SM_V + tid * 16, (const char*)(v + tid * 4));
        CP_COMMIT();
    }

    // ---- A: enc rows [blk*128, +128): fp32 -> fp16, swizzled smem ----
    const float4* asrc = (const float4*)(enc + (size_t)blockIdx.x * 128 * HDIM);
    for (int i = tid; i < 4096; i += 256) {
        int row = i >> 5, k16 = i & 31;
        float4 a = asrc[row * 64 + k16 * 2];
        float4 b = asrc[row * 64 + k16 * 2 + 1];
        __half2 t0 = __floats2half2_rn(a.x, a.y);
        __half2 t1 = __floats2half2_rn(a.z, a.w);
        __half2 t2 = __floats2half2_rn(b.x, b.y);
        __half2 t3 = __floats2half2_rn(b.z, b.w);
        uint4 val;
        val.x = *reinterpret_cast<uint32_t*>(&t0);
        val.y = *reinterpret_cast<uint32_t*>(&t1);
        val.z = *reinterpret_cast<uint32_t*>(&t2);
        val.w = *reinterpret_cast<uint32_t*>(&t3);
        *reinterpret_cast<uint4*>(smem + SM_A + row * 512 + ((k16 ^ (row & 7)) << 4)) = val;
    }

    // ---- per-lane ldmatrix addressing (layout validated R2/R3) ----
    int arow = wid * 16 + (lid & 7) + (lid & 8);
    uint32_t aoff = sb + SM_A + arow * 512;
    uint32_t asw  = (uint32_t)(arow & 7);
    uint32_t ahalf = (lid >> 4) & 1;
    int bn = (lid & 7) + (((lid >> 4) & 1) << 3);
    uint32_t boff = sb + SM_B + bn * 512;
    uint32_t bsw  = (uint32_t)(bn & 7);
    uint32_t bhalf = (lid >> 3) & 1;

    float rs[2] = {0.f, 0.f};   // partial scores for rows (gid), (gid+8)

    for (int c = 0; c < 8; c++) {
        if (c > 0) {
            __syncthreads();    // previous chunk's B/p consumers done
            const char* bsrc = (const char*)(g_W2h + (size_t)c * 64 * HDIM);
            for (int i = tid; i < 2048; i += 256) {
                int row = i >> 5, k16 = i & 31;
                cp_async16(sb + SM_B + row * 512 + ((k16 ^ (row & 7)) << 4), bsrc + i * 16);
            }
            for (int i = tid; i < 512; i += 256) {
                int pb = i >> 4, j16 = i & 15;
                cp_async16(sb + SM_P + pb * 272 + j16 * 16,
                           (const char*)(g_p + pb * 512 + c * 64 + j16 * 4));
            }
            CP_COMMIT();
        }
        CP_WAIT0();
        __syncthreads();        // B/p/v (and A stores on c==0) visible

        float acc[8][4];        // fp32 master accumulators
        #pragma unroll
        for (int j = 0; j < 8; j++)
            #pragma unroll
            for (int r = 0; r < 4; r++) acc[j][r] = 0.f;

        uint32_t hc[8][2];      // fp16x2 accumulators (zeroed every K=128)
        #pragma unroll
        for (int j = 0; j < 8; j++) { hc[j][0] = 0u; hc[j][1] = 0u; }

        #pragma unroll
        for (int kk = 0; kk < 16; kk++) {
            uint32_t ak = (((2u * kk + ahalf) ^ asw) << 4);
            uint32_t bk = (((2u * kk + bhalf) ^ bsw) << 4);
            uint32_t a[4], br[16];
            asm volatile("ldmatrix.sync.aligned.m8n8.x4.shared.b16 {%0,%1,%2,%3}, [%4];"
                : "=r"(a[0]), "=r"(a[1]), "=r"(a[2]), "=r"(a[3]) : "r"(aoff + ak));
            #pragma unroll
            for (int t = 0; t < 4; t++) {
                asm volatile("ldmatrix.sync.aligned.m8n8.x4.shared.b16 {%0,%1,%2,%3}, [%4];"
                    : "=r"(br[4 * t]), "=r"(br[4 * t + 1]),
                      "=r"(br[4 * t + 2]), "=r"(br[4 * t + 3])
                    : "r"(boff + (uint32_t)t * 8192 + bk));
            }
            #pragma unroll
            for (int j = 0; j < 8; j++) {
                asm volatile(
                    "mma.sync.aligned.m16n8k16.row.col.f16.f16.f16.f16 "
                    "{%0,%1}, {%2,%3,%4,%5}, {%6,%7}, {%0,%1};"
                    : "+r"(hc[j][0]), "+r"(hc[j][1])
                    : "r"(a[0]), "r"(a[1]), "r"(a[2]), "r"(a[3]),
                      "r"(br[2 * j]), "r"(br[2 * j + 1]));
            }
            // split-K: promote fp16 partials to fp32 every K=128 (kk==7, kk==15)
            if ((kk & 7) == 7) {
                #pragma unroll
                for (int j = 0; j < 8; j++) {
                    float2 f0 = __half22float2(*reinterpret_cast<__half2*>(&hc[j][0]));
                    float2 f1 = __half22float2(*reinterpret_cast<__half2*>(&hc[j][1]));
                    acc[j][0] += f0.x;  acc[j][1] += f0.y;   // row gid,   cols tg*2, tg*2+1
                    acc[j][2] += f1.x;  acc[j][3] += f1.y;   // row gid+8
                    hc[j][0] = 0u; hc[j][1] = 0u;
                }
            }
        }

        // ---- fused epilogue: += v[col] * tanh(acc + p[b][col]) ----
        const float* vc = v_s + c * 64;
        #pragma unroll
        for (int r = 0; r < 4; r++) {
            int rh = r >> 1;
            int bix = (wid * 16 + gid + (rh << 3)) & 31;
            const float* pr = p_s + bix * 68;
            float s = 0.f;
            #pragma unroll
            for (int j = 0; j < 8; j++) {
                int lcol = j * 8 + tg * 2 + (r & 1);
                s += vc[lcol] * tanh_fast(acc[j][r] + pr[lcol]);
            }
            rs[rh] += s;
        }
    }

    // quad reduction (lanes share gid, differ in tg)
    #pragma unroll
    for (int h = 0; h < 2; h++) {
        float x = rs[h];
        x += __shfl_xor_sync(0xFFFFFFFF, x, 1);
        x += __shfl_xor_sync(0xFFFFFFFF, x, 2);
        rs[h] = x;
    }
    if (tg == 0) {
        int m = blockIdx.x * 128 + wid * 16 + gid;
        float e0 = __expf(rs[0]);
        float e1 = __expf(rs[1]);
        g_e[m]     = e0;
        g_e[m + 8] = e1;
        atomicAdd(&bsum[m & 31], e0);
        atomicAdd(&bsum[(m + 8) & 31], e1);
    }
    __syncthreads();
    if (tid < 32) atomicAdd(&g_sum[tid], bsum[tid]);
}

// ---------------- kernel 3: masked edge scatter-add with softmax divide, x0.1 ----------------
__global__ void scatter_kernel(const int* __restrict__ esrc,
                               const int* __restrict__ edst,
                               float* __restrict__ out) {
    int i = blockIdx.x * 256 + threadIdx.x;
    if (i >= BATCH * EDGES) return;
    int b = i >> 13;                    // EDGES = 8192
    int s = esrc[i], d = edst[i];
    if (d != s + 1) {
        float w = 0.1f * __fdividef(g_e[s * 32 + b], g_sum[b]);
        atomicAdd(out + b * TSTEPS + d, w);
    }
}

// ---------------- host launch ----------------
extern "C" void kernel_launch(void* const* d_in, const int* in_sizes, int n_in,
                              void* d_out, int out_size) {
    const float* hidden = (const float*)d_in[0];
    const float* enc    = (const float*)d_in[1];
    const int*   esrc   = (const int*)d_in[2];
    const int*   edst   = (const int*)d_in[3];
    const float* W      = (const float*)d_in[4];
    const float* ba     = (const float*)d_in[5];
    const float* v      = (const float*)d_in[6];
    float* out = (float*)d_out;

    cudaFuncSetAttribute(attn_gemm_kernel,
                         cudaFuncAttributeMaxDynamicSharedMemorySize, SM_TOTAL);

    prep_p_kernel<<<2048, 256>>>(hidden, W, ba);
    prep_w2_kernel<<<512, 256>>>(W, out);
    attn_gemm_kernel<<<MTOT / 128, 256, SM_TOTAL>>>(enc, v);
    scatter_kernel<<<(BATCH * EDGES + 255) / 256, 256>>>(esrc, edst, out);
}